// round 16
// baseline (speedup 1.0000x reference)
#include <cuda_runtime.h>
#include <cuda_fp16.h>
#include <math.h>
#include <stdint.h>

// ---------------------------------------------------------------------------
// Problem constants
#define BATCH 4
#define NOBJ  256
#define HDIM  512
#define CD1   256      // collision hidden 1 (= K of pair GEMM)
#define CD2   128      // collision hidden 2 (= N of pair GEMM)

// Output layout (float32, reference return order)
#define OFF_MASS 0
#define OFF_FRIC 1024
#define OFF_ELAS 2048
#define OFF_DENS 3072
#define OFF_VEL  4096
#define OFF_FRC  7168
#define OFF_COL  10240

// Scratch (device globals; no allocation allowed)
__device__ float g_H[BATCH * NOBJ * HDIM];            // relu(x@pp_w1+b1), fp32
// [A | B] halves as packed half2: row-major, 256 u32 per row (512 halfs)
__device__ __align__(16) uint32_t g_ABh[BATCH * NOBJ * 256];   // 1 MB
// W2 as fp16, b-fragment packed: entry e=((kslg*128+n)*4+t4), uint2 =
// { half2(W2[k][n],W2[k+1][n]), half2(W2[k+8][n],W2[k+9][n]) }, k=kslg*16+2*t4
__device__ __align__(16) uint2 g_W2pkh[16 * 128 * 4];          // 64 KB

// ---------------------------------------------------------------------------
// m16n8k8 tf32 warp MMA (heads GEMM). Operands are raw fp32 bits: HW reads
// only the tf32 field (low 13 mantissa bits ignored -> RZ-truncated tf32).
static __device__ __forceinline__ void mma_tf32(
    float c[4], const uint32_t a[4], const uint32_t b[2])
{
    asm volatile(
        "mma.sync.aligned.m16n8k8.row.col.f32.tf32.tf32.f32 "
        "{%0,%1,%2,%3}, {%4,%5,%6,%7}, {%8,%9}, {%0,%1,%2,%3};\n"
        : "+f"(c[0]), "+f"(c[1]), "+f"(c[2]), "+f"(c[3])
        : "r"(a[0]), "r"(a[1]), "r"(a[2]), "r"(a[3]),
          "r"(b[0]), "r"(b[1]));
}

// m16n8k16 fp16 warp MMA, fp32 accum (pair GEMM)
static __device__ __forceinline__ void mma_f16(
    float c[4], const uint32_t a[4], const uint32_t b[2])
{
    asm volatile(
        "mma.sync.aligned.m16n8k16.row.col.f32.f16.f16.f32 "
        "{%0,%1,%2,%3}, {%4,%5,%6,%7}, {%8,%9}, {%0,%1,%2,%3};\n"
        : "+f"(c[0]), "+f"(c[1]), "+f"(c[2]), "+f"(c[3])
        : "r"(a[0]), "r"(a[1]), "r"(a[2]), "r"(a[3]),
          "r"(b[0]), "r"(b[1]));
}

static __device__ __forceinline__ void cp_async16(uint32_t dst_smem, const void* src) {
    asm volatile("cp.async.cg.shared.global [%0], [%1], 16;"
                 :: "r"(dst_smem), "l"(src) : "memory");
}

static __device__ __forceinline__ uint32_t pack_h2(float lo, float hi) {
    __half2 h = __floats2half2_rn(lo, hi);
    return *(uint32_t*)&h;
}

// relu(a + b) on packed half2 (u32 views)
static __device__ __forceinline__ uint32_t hadd2_relu(uint32_t a, uint32_t b) {
    __half2 s = __hadd2(*(__half2*)&a, *(__half2*)&b);
    __half2 z = __float2half2_rn(0.f);
    __half2 r = __hmax2(s, z);
    return *(uint32_t*)&r;
}

// ---------------------------------------------------------------------------
// Kernel 1: heads GEMM, tf32 mma.sync, 4-buffer cp.async pipeline (2 chunks
// in flight -> copy latency fully hidden behind MMA of older chunks).
// CTA tile 64(M) x 128(N), K=512 in 16 chunks of 32; 1 sync per chunk.
// grid (4 nblk, 16 mblk, 2): z=0 -> g_H (fp32) = relu(x@pp_w1 + pp_b1)
//                            z=1 -> g_ABh (fp16) = x@[cd_w1a|cd_w1b] (+cd_b1 on A)
// smem: xbuf 4 x 9216 (64 rows x 144 B), wbuf 4 x 17408 (32 rows x 544 B),
//       sbias 512 -> total 107008 B
// ---------------------------------------------------------------------------
#define HX_BUF 9216
#define HW_BUF 17408
#define HW_BASE 36864
#define HEADS_SMEM 107008

__global__ void __launch_bounds__(256, 2) heads_gemm(
    const float* __restrict__ x,
    const float* __restrict__ pp_w1, const float* __restrict__ pp_b1,
    const float* __restrict__ cd_w1, const float* __restrict__ cd_b1)
{
    extern __shared__ char sm[];
    float* sbias = (float*)(sm + 106496);

    const int tid = threadIdx.x;
    const int wid = tid >> 5, lane = tid & 31;
    const int g = lane >> 2, t4 = lane & 3;
    const int wm = wid & 1, wn = wid >> 1;     // warp grid 2(m) x 4(n)

    const int n0 = blockIdx.x * 128;
    const int m0 = blockIdx.y * 64;
    const int z  = blockIdx.z;

    const float* Wbase;
    int wstride, ncol0;
    if (z == 0) { Wbase = pp_w1; wstride = 512; ncol0 = n0; }
    else        { Wbase = cd_w1 + (n0 >= 256 ? 512 * 256 : 0); wstride = 256; ncol0 = n0 & 255; }

    if (tid < 128) {
        float bv;
        if (z == 0) bv = pp_b1[n0 + tid];
        else        bv = (n0 + tid < 256) ? cd_b1[n0 + tid] : 0.f;
        sbias[tid] = bv;
    }

    const uint32_t smb = (uint32_t)__cvta_generic_to_shared(sm);

    // issue cp.async copies for chunk c into buffer c%4, then commit
    auto issue_chunk = [&](int c) {
        const int k0 = c * 32;
        const uint32_t xs = smb + (c & 3) * HX_BUF;
        const uint32_t ws = smb + HW_BASE + (c & 3) * HW_BUF;
        #pragma unroll
        for (int v = 0; v < 2; v++) {              // x: 64 rows x 8 segs
            int s = v * 256 + tid;
            int r = s >> 3, sg = s & 7;
            cp_async16(xs + r * 144 + sg * 16,
                       x + (m0 + r) * HDIM + k0 + sg * 4);
        }
        #pragma unroll
        for (int v = 0; v < 4; v++) {              // W: 32 rows x 32 segs
            int s = v * 256 + tid;
            int r = s >> 5, sg = s & 31;
            cp_async16(ws + r * 544 + sg * 16,
                       Wbase + (k0 + r) * wstride + ncol0 + sg * 4);
        }
        asm volatile("cp.async.commit_group;" ::: "memory");
    };

    float acc[2][4][4];
    #pragma unroll
    for (int mt = 0; mt < 2; mt++)
        #pragma unroll
        for (int nt = 0; nt < 4; nt++)
            #pragma unroll
            for (int r = 0; r < 4; r++) acc[mt][nt][r] = 0.f;

    issue_chunk(0);
    issue_chunk(1);

    for (int c = 0; c < 16; c++) {
        if (c + 2 < 16) {
            issue_chunk(c + 2);
            asm volatile("cp.async.wait_group 2;" ::: "memory");
        } else if (c + 1 < 16) {
            asm volatile("cp.async.wait_group 1;" ::: "memory");
        } else {
            asm volatile("cp.async.wait_group 0;" ::: "memory");
        }
        __syncthreads();   // chunk c visible; buf (c+2)%4's readers (c-2) done

        const uint32_t* xa = (const uint32_t*)(sm + (c & 3) * HX_BUF);
        const uint32_t* wb = (const uint32_t*)(sm + HW_BASE + (c & 3) * HW_BUF);

        #pragma unroll
        for (int ks = 0; ks < 4; ks++) {
            const int kb = ks * 8;
            uint32_t a[2][4], bf[4][2];
            #pragma unroll
            for (int mt = 0; mt < 2; mt++) {
                int base = (wm * 32 + mt * 16 + g) * 36 + kb + t4;
                a[mt][0] = xa[base];
                a[mt][1] = xa[base + 8 * 36];
                a[mt][2] = xa[base + 4];
                a[mt][3] = xa[base + 8 * 36 + 4];
            }
            #pragma unroll
            for (int nt = 0; nt < 4; nt++) {
                int nb = wn * 32 + nt * 8 + g;
                bf[nt][0] = wb[(kb + t4) * 136 + nb];
                bf[nt][1] = wb[(kb + t4 + 4) * 136 + nb];
            }
            #pragma unroll
            for (int mt = 0; mt < 2; mt++)
                #pragma unroll
                for (int nt = 0; nt < 4; nt++)
                    mma_tf32(acc[mt][nt], a[mt], bf[nt]);
        }
    }

    #pragma unroll
    for (int mt = 0; mt < 2; mt++) {
        int row = m0 + wm * 32 + mt * 16 + g;
        #pragma unroll
        for (int nt = 0; nt < 4; nt++) {
            int cl = wn * 32 + nt * 8 + 2 * t4;      // local col (even)
            float b0v = sbias[cl], b1v = sbias[cl + 1];
            float v0 = acc[mt][nt][0] + b0v;
            float v1 = acc[mt][nt][1] + b1v;
            float v2 = acc[mt][nt][2] + b0v;
            float v3 = acc[mt][nt][3] + b1v;
            if (z == 0) {
                v0 = fmaxf(v0, 0.f); v1 = fmaxf(v1, 0.f);
                v2 = fmaxf(v2, 0.f); v3 = fmaxf(v3, 0.f);
                *(float2*)&g_H[row * 512 + n0 + cl]       = make_float2(v0, v1);
                *(float2*)&g_H[(row + 8) * 512 + n0 + cl] = make_float2(v2, v3);
            } else {
                g_ABh[row * 256 + ((n0 + cl) >> 1)]       = pack_h2(v0, v1);
                g_ABh[(row + 8) * 256 + ((n0 + cl) >> 1)] = pack_h2(v2, v3);
            }
        }
    }
}

// ---------------------------------------------------------------------------
// Kernel 2: small heads + fused W2 fragment pack (unchanged).
// ---------------------------------------------------------------------------
__global__ void __launch_bounds__(256) small_heads(
    const float* __restrict__ x,
    const float* __restrict__ pp_w2, const float* __restrict__ pp_b2,
    const float* __restrict__ vel_w, const float* __restrict__ vel_b,
    const float* __restrict__ frc_w, const float* __restrict__ frc_b,
    const float* __restrict__ cd_w2,
    float* __restrict__ out)
{
    __shared__ float sw[HDIM * 10];
    const int tid  = threadIdx.x;
    const int row0 = blockIdx.x * 8;

    // fused prep_w2t: 64 entries per block (128 x 64 = 8192 exact)
    if (tid < 64) {
        int e = blockIdx.x * 64 + tid;
        int t4 = e & 3, n = (e >> 2) & 127, kslg = e >> 9;
        int k = kslg * 16 + 2 * t4;
        uint2 v;
        v.x = pack_h2(cd_w2[k * CD2 + n],       cd_w2[(k + 1) * CD2 + n]);
        v.y = pack_h2(cd_w2[(k + 8) * CD2 + n], cd_w2[(k + 9) * CD2 + n]);
        g_W2pkh[e] = v;
    }

    for (int idx = tid; idx < HDIM * 10; idx += 256) {
        int k = idx / 10, q = idx - k * 10;
        float v;
        if      (q < 4) v = pp_w2[k * 128 + q];
        else if (q < 7) v = vel_w[k * 3 + (q - 4)];
        else            v = frc_w[k * 3 + (q - 7)];
        sw[idx] = v;
    }
    __syncthreads();

    const int warp = tid >> 5, lane = tid & 31;
    const int row  = row0 + warp;
    const float* srcH = g_H + row * HDIM;
    const float* srcX = x   + row * HDIM;

    for (int q = 0; q < 10; q++) {
        const float* src = (q < 4) ? srcH : srcX;
        float sum = 0.f;
        for (int k = lane; k < HDIM; k += 32)
            sum = fmaf(src[k], sw[k * 10 + q], sum);
        #pragma unroll
        for (int o = 16; o > 0; o >>= 1)
            sum += __shfl_xor_sync(0xffffffffu, sum, o);
        if (lane == 0) {
            if (q < 4) {
                float s = 1.f / (1.f + expf(-(sum + pp_b2[q])));
                if      (q == 0) out[OFF_MASS + row] = s * 100.f;
                else if (q == 1) out[OFF_FRIC + row] = s;
                else if (q == 2) out[OFF_ELAS + row] = s;
                else             out[OFF_DENS + row] = s * 10.f;
            } else if (q < 7) {
                out[OFF_VEL + row * 3 + (q - 4)] = sum + vel_b[q - 4];
            } else {
                out[OFF_FRC + row * 3 + (q - 7)] = sum + frc_b[q - 7];
            }
        }
    }
}

// ---------------------------------------------------------------------------
// Kernel 3: pairwise collisions via fp16 m16n8k16. CTA: 128 pairs (16i x 8j)
// x 128 cols, K=256 in 4 chunks. NEW: build(c+1) lives in the SAME barrier
// region as MMA(c) (different h1 buffers, read-only sources) so the SM can
// interleave HADD2/STS with HMMA/LDS instead of serializing the phases.
// ---------------------------------------------------------------------------
#define PAIR_SMEM 114560

__global__ void __launch_bounds__(256, 2) pair_kernel(
    const float* __restrict__ cd_b2, const float* __restrict__ cd_w3,
    const float* __restrict__ cd_b3, float* __restrict__ out)
{
    extern __shared__ char sm[];
    uint32_t* sA16 = (uint32_t*)(sm + 98304);
    uint32_t* sB16 = (uint32_t*)(sm + 106752);
    float*    b2s  = (float*)(sm + 110976);
    float*    w3s  = (float*)(sm + 111488);
    float*    sred = (float*)(sm + 112000);

    const int tid = threadIdx.x;
    const int wid = tid >> 5, lane = tid & 31;
    const int g = lane >> 2, t4 = lane & 3;
    const int wm = wid & 1, wn = wid >> 1;   // warp grid 2(m) x 4(n)

    int b = blockIdx.x / 272;
    int t = blockIdx.x % 272;
    int bi = 0, rem = t;
    while (rem >= 32 - 2 * bi) { rem -= 32 - 2 * bi; bi++; }
    int bj = 2 * bi + rem;
    const int i0 = bi * 16, j0 = bj * 8;
    const int rowbase = b * NOBJ;

    const uint32_t w2_smem = (uint32_t)__cvta_generic_to_shared(sm + 32768);
    {
        const uint4* src = (const uint4*)g_W2pkh;
        #pragma unroll
        for (int v = 0; v < 16; v++) {
            int e = v * 256 + tid;
            cp_async16(w2_smem + e * 16, src + e);
        }
    }

    if (tid < CD2) { b2s[tid] = cd_b2[tid]; w3s[tid] = cd_w3[tid]; }

    #pragma unroll
    for (int v = 0; v < 8; v++) {
        int idx = v * 256 + tid;
        int r = idx >> 7, kk = idx & 127;
        sA16[r * 132 + kk] = g_ABh[(rowbase + i0 + r) * 256 + kk];
    }
    #pragma unroll
    for (int v = 0; v < 4; v++) {
        int idx = v * 256 + tid;
        int r = idx >> 7, kk = idx & 127;
        sB16[r * 132 + kk] = g_ABh[(rowbase + j0 + r) * 256 + 128 + kk];
    }

    // build h1 chunk c as fp16 fragment quads: relu(A+B) via HADD2/HMAX2
    auto build_chunk = [&](int c) {
        uint4* hq = (uint4*)(sm + (c & 1) * 16384);
        const int hb0 = c * 32;
        #pragma unroll
        for (int v = 0; v < 4; v++) {
            int q = v * 256 + tid;
            int t4q = q & 3, gq = (q >> 2) & 7, kslq = (q >> 5) & 3, mbq = q >> 7;
            int hb = hb0 + kslq * 8 + t4q;
            const uint32_t* Ar0 = sA16 + (2 * mbq) * 132 + hb;
            const uint32_t* Ar1 = Ar0 + 132;
            const uint32_t* Br  = sB16 + gq * 132 + hb;
            uint32_t bl = Br[0], bh = Br[4];
            uint4 qv;
            qv.x = hadd2_relu(Ar0[0], bl);
            qv.y = hadd2_relu(Ar1[0], bl);
            qv.z = hadd2_relu(Ar0[4], bh);
            qv.w = hadd2_relu(Ar1[4], bh);
            hq[q] = qv;
        }
    };

    float acc[4][4][4];
    #pragma unroll
    for (int mt = 0; mt < 4; mt++)
        #pragma unroll
        for (int nt = 0; nt < 4; nt++)
            #pragma unroll
            for (int r = 0; r < 4; r++) acc[mt][nt][r] = 0.f;

    __syncthreads();           // sA16/sB16 staged

    build_chunk(0);
    asm volatile("cp.async.wait_all;" ::: "memory");   // W2 resident
    __syncthreads();           // h1(0) + W2 visible

    for (int c = 0; c < 4; c++) {
        // overlap: build(c+1) into the other h1 buffer while doing MMA(c)
        if (c < 3) build_chunk(c + 1);

        const uint4* hbase = (const uint4*)(sm + (c & 1) * 16384);
        const uint2* wbase = (const uint2*)(sm + 32768 + c * 16384);
        #pragma unroll
        for (int ksl = 0; ksl < 4; ksl++) {
            uint32_t a[4][4], bf[4][2];
            #pragma unroll
            for (int mt = 0; mt < 4; mt++) {
                int mbf = wm * 4 + mt;
                uint4 av = hbase[((mbf * 4 + ksl) * 8 + g) * 4 + t4];
                a[mt][0] = av.x; a[mt][1] = av.y; a[mt][2] = av.z; a[mt][3] = av.w;
            }
            #pragma unroll
            for (int nt = 0; nt < 4; nt++) {
                int n = wn * 32 + nt * 8 + g;
                uint2 bv = wbase[(ksl * 128 + n) * 4 + t4];
                bf[nt][0] = bv.x; bf[nt][1] = bv.y;
            }
            #pragma unroll
            for (int mt = 0; mt < 4; mt++)
                #pragma unroll
                for (int nt = 0; nt < 4; nt++)
                    mma_f16(acc[mt][nt], a[mt], bf[nt]);
        }
        __syncthreads();   // orders build(c+1) before MMA(c+1), MMA(c) before build(c+2)
    }

    #pragma unroll
    for (int mt = 0; mt < 4; mt++) {
        float s0 = 0.f, s1 = 0.f;
        #pragma unroll
        for (int nt = 0; nt < 4; nt++) {
            int cl = wn * 32 + nt * 8 + 2 * t4;
            float h;
            h = fmaxf(acc[mt][nt][0] + b2s[cl],     0.f); s0 = fmaf(h, w3s[cl],     s0);
            h = fmaxf(acc[mt][nt][1] + b2s[cl + 1], 0.f); s0 = fmaf(h, w3s[cl + 1], s0);
            h = fmaxf(acc[mt][nt][2] + b2s[cl],     0.f); s1 = fmaf(h, w3s[cl],     s1);
            h = fmaxf(acc[mt][nt][3] + b2s[cl + 1], 0.f); s1 = fmaf(h, w3s[cl + 1], s1);
        }
        s0 += __shfl_xor_sync(0xffffffffu, s0, 1);
        s0 += __shfl_xor_sync(0xffffffffu, s0, 2);
        s1 += __shfl_xor_sync(0xffffffffu, s1, 1);
        s1 += __shfl_xor_sync(0xffffffffu, s1, 2);
        if (t4 == 0) {
            int p = wm * 64 + mt * 16 + g;
            sred[p * 5 + wn]       = s0;
            sred[(p + 8) * 5 + wn] = s1;
        }
    }
    __syncthreads();

    if (tid < 128) {
        float sum = sred[tid * 5] + sred[tid * 5 + 1] +
                    sred[tid * 5 + 2] + sred[tid * 5 + 3] + cd_b3[0];
        int i = i0 + (tid >> 3);
        int j = j0 + (tid & 7);
        float* cm = out + OFF_COL + b * (NOBJ * NOBJ);
        if (i < j) {
            float prob = 1.f / (1.f + expf(-sum));
            cm[i * NOBJ + j] = prob;
            cm[j * NOBJ + i] = prob;
        } else if (i == j) {
            cm[i * NOBJ + i] = 0.f;   // d_out poisoned; diagonal must be 0
        }
    }
}

// ---------------------------------------------------------------------------
extern "C" void kernel_launch(void* const* d_in, const int* in_sizes, int n_in,
                              void* d_out, int out_size)
{
    (void)in_sizes; (void)n_in; (void)out_size;
    const float* x     = (const float*)d_in[0];
    const float* pp_w1 = (const float*)d_in[1];
    const float* pp_b1 = (const float*)d_in[2];
    const float* pp_w2 = (const float*)d_in[3];
    const float* pp_b2 = (const float*)d_in[4];
    const float* cd_w1 = (const float*)d_in[5];
    const float* cd_b1 = (const float*)d_in[6];
    const float* cd_w2 = (const float*)d_in[7];
    const float* cd_b2 = (const float*)d_in[8];
    const float* cd_w3 = (const float*)d_in[9];
    const float* cd_b3 = (const float*)d_in[10];
    const float* vel_w = (const float*)d_in[11];
    const float* vel_b = (const float*)d_in[12];
    const float* frc_w = (const float*)d_in[13];
    const float* frc_b = (const float*)d_in[14];
    float* out = (float*)d_out;

    cudaFuncSetAttribute(heads_gemm, cudaFuncAttributeMaxDynamicSharedMemorySize, HEADS_SMEM);
    cudaFuncSetAttribute(pair_kernel, cudaFuncAttributeMaxDynamicSharedMemorySize, PAIR_SMEM);

    heads_gemm<<<dim3(4, 16, 2), 256, HEADS_SMEM>>>(x, pp_w1, pp_b1, cd_w1, cd_b1);
    small_heads<<<128, 256>>>(x, pp_w2, pp_b2, vel_w, vel_b, frc_w, frc_b, cd_w2, out);
    pair_kernel<<<4 * 272, 256, PAIR_SMEM>>>(cd_b2, cd_w3, cd_b3, out);
}

// round 17
// speedup vs baseline: 1.1216x; 1.1216x over previous
#include <cuda_runtime.h>
#include <cuda_fp16.h>
#include <math.h>
#include <stdint.h>

// ---------------------------------------------------------------------------
// Problem constants
#define BATCH 4
#define NOBJ  256
#define HDIM  512
#define CD1   256
#define CD2   128

// Output layout (float32, reference return order)
#define OFF_MASS 0
#define OFF_FRIC 1024
#define OFF_ELAS 2048
#define OFF_DENS 3072
#define OFF_VEL  4096
#define OFF_FRC  7168
#define OFF_COL  10240

// Scratch (device globals; no allocation allowed)
__device__ float g_H[BATCH * NOBJ * HDIM];            // relu(x@pp_w1+b1), fp32
__device__ __align__(16) uint32_t g_ABh[BATCH * NOBJ * 256];   // [A|B] fp16 half2
__device__ __align__(16) uint2 g_W2pkh[16 * 128 * 4];          // W2 fp16 b-frag packed

// ---------------------------------------------------------------------------
// m16n8k8 tf32 warp MMA. Operands raw fp32 bits (RZ-truncated tf32).
static __device__ __forceinline__ void mma_tf32(
    float c[4], const uint32_t a[4], const uint32_t b[2])
{
    asm volatile(
        "mma.sync.aligned.m16n8k8.row.col.f32.tf32.tf32.f32 "
        "{%0,%1,%2,%3}, {%4,%5,%6,%7}, {%8,%9}, {%0,%1,%2,%3};\n"
        : "+f"(c[0]), "+f"(c[1]), "+f"(c[2]), "+f"(c[3])
        : "r"(a[0]), "r"(a[1]), "r"(a[2]), "r"(a[3]),
          "r"(b[0]), "r"(b[1]));
}

// m16n8k16 fp16 warp MMA, fp32 accum
static __device__ __forceinline__ void mma_f16(
    float c[4], const uint32_t a[4], const uint32_t b[2])
{
    asm volatile(
        "mma.sync.aligned.m16n8k16.row.col.f32.f16.f16.f32 "
        "{%0,%1,%2,%3}, {%4,%5,%6,%7}, {%8,%9}, {%0,%1,%2,%3};\n"
        : "+f"(c[0]), "+f"(c[1]), "+f"(c[2]), "+f"(c[3])
        : "r"(a[0]), "r"(a[1]), "r"(a[2]), "r"(a[3]),
          "r"(b[0]), "r"(b[1]));
}

static __device__ __forceinline__ void cp_async16(uint32_t dst_smem, const void* src) {
    asm volatile("cp.async.cg.shared.global [%0], [%1], 16;"
                 :: "r"(dst_smem), "l"(src) : "memory");
}

static __device__ __forceinline__ uint32_t pack_h2(float lo, float hi) {
    __half2 h = __floats2half2_rn(lo, hi);
    return *(uint32_t*)&h;
}

static __device__ __forceinline__ uint32_t hadd2_relu(uint32_t a, uint32_t b) {
    __half2 s = __hadd2(*(__half2*)&a, *(__half2*)&b);
    __half2 z = __float2half2_rn(0.f);
    __half2 r = __hmax2(s, z);
    return *(uint32_t*)&r;
}

// ---------------------------------------------------------------------------
// Kernel 1: heads GEMM, tf32 mma.sync, 4-buffer cp.async pipeline.
// CTA tile 64(M) x 64(N), K=512 in 16 chunks of 32; warp grid 4(m) x 2(n).
// grid (8 nblk, 16 mblk, 2) = 512 CTA-equivalents... (8*16*2 = 256 CTAs).
// z=0 -> g_H = relu(x@pp_w1+b1); z=1 -> g_ABh = x@[cd_w1a|cd_w1b] (+b1 on A).
// Also: z=0,y=0 blocks (8) pack g_W2pkh (4 entries/thread).
// smem: xbuf 4 x 9216 (64r x 144B), wbuf 4 x 9216 (32r x 288B), bias 256
//   -> 73984 B  => 3 CTAs/SM.
// ---------------------------------------------------------------------------
#define HX_BUF 9216
#define HWB    9216
#define HW_BASE 36864
#define HEADS_SMEM 73984

__global__ void __launch_bounds__(256, 3) heads_gemm(
    const float* __restrict__ x,
    const float* __restrict__ pp_w1, const float* __restrict__ pp_b1,
    const float* __restrict__ cd_w1, const float* __restrict__ cd_b1,
    const float* __restrict__ cd_w2)
{
    extern __shared__ char sm[];
    float* sbias = (float*)(sm + 73728);

    const int tid = threadIdx.x;
    const int wid = tid >> 5, lane = tid & 31;
    const int g = lane >> 2, t4 = lane & 3;
    const int wm = wid & 3, wn = wid >> 2;     // warp grid 4(m) x 2(n)

    const int n0 = blockIdx.x * 64;
    const int m0 = blockIdx.y * 64;
    const int z  = blockIdx.z;

    // fused W2 pack: 8 blocks (z=0, y=0) x 256 thr x 4 entries = 8192 exact
    if (z == 0 && blockIdx.y == 0) {
        #pragma unroll
        for (int v = 0; v < 4; v++) {
            int e = v * 2048 + blockIdx.x * 256 + tid;
            int t4e = e & 3, n = (e >> 2) & 127, kslg = e >> 9;
            int k = kslg * 16 + 2 * t4e;
            uint2 w;
            w.x = pack_h2(cd_w2[k * CD2 + n],       cd_w2[(k + 1) * CD2 + n]);
            w.y = pack_h2(cd_w2[(k + 8) * CD2 + n], cd_w2[(k + 9) * CD2 + n]);
            g_W2pkh[e] = w;
        }
    }

    const float* Wbase;
    int wstride, ncol0;
    if (z == 0) { Wbase = pp_w1; wstride = 512; ncol0 = n0; }
    else        { Wbase = cd_w1 + (n0 >= 256 ? 512 * 256 : 0); wstride = 256; ncol0 = n0 & 255; }

    if (tid < 64) {
        float bv;
        if (z == 0) bv = pp_b1[n0 + tid];
        else        bv = (n0 + tid < 256) ? cd_b1[n0 + tid] : 0.f;
        sbias[tid] = bv;
    }

    const uint32_t smb = (uint32_t)__cvta_generic_to_shared(sm);

    auto issue_chunk = [&](int c) {
        const int k0 = c * 32;
        const uint32_t xs = smb + (c & 3) * HX_BUF;
        const uint32_t ws = smb + HW_BASE + (c & 3) * HWB;
        #pragma unroll
        for (int v = 0; v < 2; v++) {              // x: 64 rows x 8 segs
            int s = v * 256 + tid;
            int r = s >> 3, sg = s & 7;
            cp_async16(xs + r * 144 + sg * 16,
                       x + (m0 + r) * HDIM + k0 + sg * 4);
        }
        #pragma unroll
        for (int v = 0; v < 2; v++) {              // W: 32 rows x 16 segs
            int s = v * 256 + tid;
            int r = s >> 4, sg = s & 15;
            cp_async16(ws + r * 288 + sg * 16,
                       Wbase + (k0 + r) * wstride + ncol0 + sg * 4);
        }
        asm volatile("cp.async.commit_group;" ::: "memory");
    };

    float acc[4][4];                    // 1 m-tile (16 rows) x 4 n-tiles (8 cols)
    #pragma unroll
    for (int nt = 0; nt < 4; nt++)
        #pragma unroll
        for (int r = 0; r < 4; r++) acc[nt][r] = 0.f;

    issue_chunk(0);
    issue_chunk(1);

    for (int c = 0; c < 16; c++) {
        if (c + 2 < 16) {
            issue_chunk(c + 2);
            asm volatile("cp.async.wait_group 2;" ::: "memory");
        } else if (c + 1 < 16) {
            asm volatile("cp.async.wait_group 1;" ::: "memory");
        } else {
            asm volatile("cp.async.wait_group 0;" ::: "memory");
        }
        __syncthreads();

        const uint32_t* xa = (const uint32_t*)(sm + (c & 3) * HX_BUF);
        const uint32_t* wb = (const uint32_t*)(sm + HW_BASE + (c & 3) * HWB);

        #pragma unroll
        for (int ks = 0; ks < 4; ks++) {
            const int kb = ks * 8;
            uint32_t a[4], bf[4][2];
            {
                int base = (wm * 16 + g) * 36 + kb + t4;
                a[0] = xa[base];
                a[1] = xa[base + 8 * 36];
                a[2] = xa[base + 4];
                a[3] = xa[base + 8 * 36 + 4];
            }
            #pragma unroll
            for (int nt = 0; nt < 4; nt++) {
                int nb = wn * 32 + nt * 8 + g;          // 0..63
                bf[nt][0] = wb[(kb + t4) * 72 + nb];     // stride 72 = 8 mod 32
                bf[nt][1] = wb[(kb + t4 + 4) * 72 + nb]; //  -> conflict-free
            }
            #pragma unroll
            for (int nt = 0; nt < 4; nt++)
                mma_tf32(acc[nt], a, bf[nt]);
        }
    }

    int row = m0 + wm * 16 + g;
    #pragma unroll
    for (int nt = 0; nt < 4; nt++) {
        int cl = wn * 32 + nt * 8 + 2 * t4;              // local col (even)
        float b0v = sbias[cl], b1v = sbias[cl + 1];
        float v0 = acc[nt][0] + b0v;
        float v1 = acc[nt][1] + b1v;
        float v2 = acc[nt][2] + b0v;
        float v3 = acc[nt][3] + b1v;
        if (z == 0) {
            v0 = fmaxf(v0, 0.f); v1 = fmaxf(v1, 0.f);
            v2 = fmaxf(v2, 0.f); v3 = fmaxf(v3, 0.f);
            *(float2*)&g_H[row * 512 + n0 + cl]       = make_float2(v0, v1);
            *(float2*)&g_H[(row + 8) * 512 + n0 + cl] = make_float2(v2, v3);
        } else {
            g_ABh[row * 256 + ((n0 + cl) >> 1)]       = pack_h2(v0, v1);
            g_ABh[(row + 8) * 256 + ((n0 + cl) >> 1)] = pack_h2(v2, v3);
        }
    }
}

// ---------------------------------------------------------------------------
// Kernel 2 (merged): blocks 0..127 = small heads; blocks 128..1215 = pair
// collisions (R13-proven structure, 32.4 us). One launch instead of two;
// small-role blocks fill SMs alongside pair's first wave.
// ---------------------------------------------------------------------------
#define PAIR_SMEM 114560

__global__ void __launch_bounds__(256, 2) tail_kernel(
    const float* __restrict__ x,
    const float* __restrict__ pp_w2, const float* __restrict__ pp_b2,
    const float* __restrict__ vel_w, const float* __restrict__ vel_b,
    const float* __restrict__ frc_w, const float* __restrict__ frc_b,
    const float* __restrict__ cd_b2, const float* __restrict__ cd_w3,
    const float* __restrict__ cd_b3,
    float* __restrict__ out)
{
    extern __shared__ char sm[];
    const int tid = threadIdx.x;

    if (blockIdx.x < 128) {
        // ---------------- small-heads role ----------------
        float* sw = (float*)sm;            // 20 KB of the 114.5 KB allocation
        const int row0 = blockIdx.x * 8;

        for (int idx = tid; idx < HDIM * 10; idx += 256) {
            int k = idx / 10, q = idx - k * 10;
            float v;
            if      (q < 4) v = pp_w2[k * 128 + q];
            else if (q < 7) v = vel_w[k * 3 + (q - 4)];
            else            v = frc_w[k * 3 + (q - 7)];
            sw[idx] = v;
        }
        __syncthreads();

        const int warp = tid >> 5, lane = tid & 31;
        const int row  = row0 + warp;
        const float* srcH = g_H + row * HDIM;
        const float* srcX = x   + row * HDIM;

        for (int q = 0; q < 10; q++) {
            const float* src = (q < 4) ? srcH : srcX;
            float sum = 0.f;
            for (int k = lane; k < HDIM; k += 32)
                sum = fmaf(src[k], sw[k * 10 + q], sum);
            #pragma unroll
            for (int o = 16; o > 0; o >>= 1)
                sum += __shfl_xor_sync(0xffffffffu, sum, o);
            if (lane == 0) {
                if (q < 4) {
                    float s = 1.f / (1.f + expf(-(sum + pp_b2[q])));
                    if      (q == 0) out[OFF_MASS + row] = s * 100.f;
                    else if (q == 1) out[OFF_FRIC + row] = s;
                    else if (q == 2) out[OFF_ELAS + row] = s;
                    else             out[OFF_DENS + row] = s * 10.f;
                } else if (q < 7) {
                    out[OFF_VEL + row * 3 + (q - 4)] = sum + vel_b[q - 4];
                } else {
                    out[OFF_FRC + row * 3 + (q - 7)] = sum + frc_b[q - 7];
                }
            }
        }
        return;
    }

    // ---------------- pair role (R13 structure) ----------------
    uint32_t* sA16 = (uint32_t*)(sm + 98304);
    uint32_t* sB16 = (uint32_t*)(sm + 106752);
    float*    b2s  = (float*)(sm + 110976);
    float*    w3s  = (float*)(sm + 111488);
    float*    sred = (float*)(sm + 112000);

    const int wid = tid >> 5, lane = tid & 31;
    const int g = lane >> 2, t4 = lane & 3;
    const int wm = wid & 1, wn = wid >> 1;   // warp grid 2(m) x 4(n)

    int pb = blockIdx.x - 128;
    int b = pb / 272;
    int t = pb % 272;
    int bi = 0, rem = t;
    while (rem >= 32 - 2 * bi) { rem -= 32 - 2 * bi; bi++; }
    int bj = 2 * bi + rem;
    const int i0 = bi * 16, j0 = bj * 8;
    const int rowbase = b * NOBJ;

    const uint32_t w2_smem = (uint32_t)__cvta_generic_to_shared(sm + 32768);
    {
        const uint4* src = (const uint4*)g_W2pkh;
        #pragma unroll
        for (int v = 0; v < 16; v++) {
            int e = v * 256 + tid;
            cp_async16(w2_smem + e * 16, src + e);
        }
    }

    if (tid < CD2) { b2s[tid] = cd_b2[tid]; w3s[tid] = cd_w3[tid]; }

    #pragma unroll
    for (int v = 0; v < 8; v++) {
        int idx = v * 256 + tid;
        int r = idx >> 7, kk = idx & 127;
        sA16[r * 132 + kk] = g_ABh[(rowbase + i0 + r) * 256 + kk];
    }
    #pragma unroll
    for (int v = 0; v < 4; v++) {
        int idx = v * 256 + tid;
        int r = idx >> 7, kk = idx & 127;
        sB16[r * 132 + kk] = g_ABh[(rowbase + j0 + r) * 256 + 128 + kk];
    }

    float acc[4][4][4];
    #pragma unroll
    for (int mt = 0; mt < 4; mt++)
        #pragma unroll
        for (int nt = 0; nt < 4; nt++)
            #pragma unroll
            for (int r = 0; r < 4; r++) acc[mt][nt][r] = 0.f;

    __syncthreads();

    for (int c = 0; c < 4; c++) {
        const int buf = c & 1;
        const int hb0 = c * 32;

        {
            uint4* hq = (uint4*)(sm + buf * 16384);
            #pragma unroll
            for (int v = 0; v < 4; v++) {
                int q = v * 256 + tid;
                int t4q = q & 3, gq = (q >> 2) & 7, kslq = (q >> 5) & 3, mbq = q >> 7;
                int hb = hb0 + kslq * 8 + t4q;
                const uint32_t* Ar0 = sA16 + (2 * mbq) * 132 + hb;
                const uint32_t* Ar1 = Ar0 + 132;
                const uint32_t* Br  = sB16 + gq * 132 + hb;
                uint32_t bl = Br[0], bh = Br[4];
                uint4 qv;
                qv.x = hadd2_relu(Ar0[0], bl);
                qv.y = hadd2_relu(Ar1[0], bl);
                qv.z = hadd2_relu(Ar0[4], bh);
                qv.w = hadd2_relu(Ar1[4], bh);
                hq[q] = qv;
            }
        }
        if (c == 0) asm volatile("cp.async.wait_all;" ::: "memory");
        __syncthreads();

        const uint4* hbase = (const uint4*)(sm + buf * 16384);
        const uint2* wbase = (const uint2*)(sm + 32768 + c * 16384);
        #pragma unroll
        for (int ksl = 0; ksl < 4; ksl++) {
            uint32_t a[4][4], bf[4][2];
            #pragma unroll
            for (int mt = 0; mt < 4; mt++) {
                int mbf = wm * 4 + mt;
                uint4 av = hbase[((mbf * 4 + ksl) * 8 + g) * 4 + t4];
                a[mt][0] = av.x; a[mt][1] = av.y; a[mt][2] = av.z; a[mt][3] = av.w;
            }
            #pragma unroll
            for (int nt = 0; nt < 4; nt++) {
                int n = wn * 32 + nt * 8 + g;
                uint2 bv = wbase[(ksl * 128 + n) * 4 + t4];
                bf[nt][0] = bv.x; bf[nt][1] = bv.y;
            }
            #pragma unroll
            for (int mt = 0; mt < 4; mt++)
                #pragma unroll
                for (int nt = 0; nt < 4; nt++)
                    mma_f16(acc[mt][nt], a[mt], bf[nt]);
        }
    }

    #pragma unroll
    for (int mt = 0; mt < 4; mt++) {
        float s0 = 0.f, s1 = 0.f;
        #pragma unroll
        for (int nt = 0; nt < 4; nt++) {
            int cl = wn * 32 + nt * 8 + 2 * t4;
            float h;
            h = fmaxf(acc[mt][nt][0] + b2s[cl],     0.f); s0 = fmaf(h, w3s[cl],     s0);
            h = fmaxf(acc[mt][nt][1] + b2s[cl + 1], 0.f); s0 = fmaf(h, w3s[cl + 1], s0);
            h = fmaxf(acc[mt][nt][2] + b2s[cl],     0.f); s1 = fmaf(h, w3s[cl],     s1);
            h = fmaxf(acc[mt][nt][3] + b2s[cl + 1], 0.f); s1 = fmaf(h, w3s[cl + 1], s1);
        }
        s0 += __shfl_xor_sync(0xffffffffu, s0, 1);
        s0 += __shfl_xor_sync(0xffffffffu, s0, 2);
        s1 += __shfl_xor_sync(0xffffffffu, s1, 1);
        s1 += __shfl_xor_sync(0xffffffffu, s1, 2);
        if (t4 == 0) {
            int p = wm * 64 + mt * 16 + g;
            sred[p * 5 + wn]       = s0;
            sred[(p + 8) * 5 + wn] = s1;
        }
    }
    __syncthreads();

    if (tid < 128) {
        float sum = sred[tid * 5] + sred[tid * 5 + 1] +
                    sred[tid * 5 + 2] + sred[tid * 5 + 3] + cd_b3[0];
        int i = i0 + (tid >> 3);
        int j = j0 + (tid & 7);
        float* cm = out + OFF_COL + b * (NOBJ * NOBJ);
        if (i < j) {
            float prob = 1.f / (1.f + expf(-sum));
            cm[i * NOBJ + j] = prob;
            cm[j * NOBJ + i] = prob;
        } else if (i == j) {
            cm[i * NOBJ + i] = 0.f;   // d_out poisoned; diagonal must be 0
        }
    }
}

// ---------------------------------------------------------------------------
extern "C" void kernel_launch(void* const* d_in, const int* in_sizes, int n_in,
                              void* d_out, int out_size)
{
    (void)in_sizes; (void)n_in; (void)out_size;
    const float* x     = (const float*)d_in[0];
    const float* pp_w1 = (const float*)d_in[1];
    const float* pp_b1 = (const float*)d_in[2];
    const float* pp_w2 = (const float*)d_in[3];
    const float* pp_b2 = (const float*)d_in[4];
    const float* cd_w1 = (const float*)d_in[5];
    const float* cd_b1 = (const float*)d_in[6];
    const float* cd_w2 = (const float*)d_in[7];
    const float* cd_b2 = (const float*)d_in[8];
    const float* cd_w3 = (const float*)d_in[9];
    const float* cd_b3 = (const float*)d_in[10];
    const float* vel_w = (const float*)d_in[11];
    const float* vel_b = (const float*)d_in[12];
    const float* frc_w = (const float*)d_in[13];
    const float* frc_b = (const float*)d_in[14];
    float* out = (float*)d_out;

    cudaFuncSetAttribute(heads_gemm, cudaFuncAttributeMaxDynamicSharedMemorySize, HEADS_SMEM);
    cudaFuncSetAttribute(tail_kernel, cudaFuncAttributeMaxDynamicSharedMemorySize, PAIR_SMEM);

    heads_gemm<<<dim3(8, 16, 2), 256, HEADS_SMEM>>>(x, pp_w1, pp_b1, cd_w1, cd_b1, cd_w2);
    tail_kernel<<<128 + 4 * 272, 256, PAIR_SMEM>>>(
        x, pp_w2, pp_b2, vel_w, vel_b, frc_w, frc_b, cd_b2, cd_w3, cd_b3, out);
}